// round 1
// baseline (speedup 1.0000x reference)
#include <cuda_runtime.h>
#include <math.h>

#define NUM_FIELDS 10
#define VOCAB      100000
#define EMBED      8
#define BATCH      16384

#define TPR            8                 // threads cooperating on one row
#define ROWS_PER_BLOCK 32
#define THREADS        (TPR * ROWS_PER_BLOCK)   // 256
#define NPAIRS         45                // 10 choose 2
#define PAIRS_PER_T    6                 // ceil(45/8)

__global__ __launch_bounds__(THREADS)
void ffm_kernel(const int*   __restrict__ x,
                const float* __restrict__ bias,
                const float* __restrict__ L,
                const float* __restrict__ V,
                float*       __restrict__ out)
{
    __shared__ int sx[ROWS_PER_BLOCK][NUM_FIELDS];
    __shared__ int sI[NPAIRS], sJ[NPAIRS];
    __shared__ int sOij[NPAIRS], sOji[NPAIRS];

    const int tid = threadIdx.x;

    // ---- build pair table (once per block) ----
    if (tid < NPAIRS) {
        int p = tid;
        int i = 0, rem = p;
        while (rem >= (NUM_FIELDS - 1 - i)) { rem -= (NUM_FIELDS - 1 - i); ++i; }
        int j = i + 1 + rem;
        sI[p] = i;
        sJ[p] = j;
        sOij[p] = (i * NUM_FIELDS + j) * VOCAB;
        sOji[p] = (j * NUM_FIELDS + i) * VOCAB;
    }

    // ---- stage x tile for this block's 32 rows ----
    const int row0 = blockIdx.x * ROWS_PER_BLOCK;
    for (int k = tid; k < ROWS_PER_BLOCK * NUM_FIELDS; k += THREADS) {
        ((int*)sx)[k] = x[row0 * NUM_FIELDS + k];
    }
    __syncthreads();

    const int r = tid / TPR;   // local row
    const int t = tid % TPR;   // slot within row group
    const int b = row0 + r;
    const int* xs = sx[r];

    float acc = 0.0f;

    // ---- second order: 45 pairs, strided by TPR, fully unrolled for MLP ----
    #pragma unroll
    for (int k = 0; k < PAIRS_PER_T; ++k) {
        const int p = t + k * TPR;
        if (p < NPAIRS) {
            const int i = sI[p];
            const int j = sJ[p];
            const float4* A  = reinterpret_cast<const float4*>(
                                   V + (size_t)(sOij[p] + xs[i]) * EMBED);
            const float4* Bv = reinterpret_cast<const float4*>(
                                   V + (size_t)(sOji[p] + xs[j]) * EMBED);
            const float4 a0 = __ldg(A);
            const float4 a1 = __ldg(A + 1);
            const float4 b0 = __ldg(Bv);
            const float4 b1 = __ldg(Bv + 1);
            acc += a0.x * b0.x + a0.y * b0.y + a0.z * b0.z + a0.w * b0.w
                 + a1.x * b1.x + a1.y * b1.y + a1.z * b1.z + a1.w * b1.w;
        }
    }

    // ---- first order: fields t, t+8 ----
    #pragma unroll
    for (int f = t; f < NUM_FIELDS; f += TPR) {
        acc += __ldg(&L[f * VOCAB + xs[f]]);
    }

    // ---- reduce across the 8-lane row group ----
    acc += __shfl_down_sync(0xffffffffu, acc, 4, 8);
    acc += __shfl_down_sync(0xffffffffu, acc, 2, 8);
    acc += __shfl_down_sync(0xffffffffu, acc, 1, 8);

    if (t == 0 && b < BATCH) {
        const float z = acc + __ldg(bias);
        out[b] = 1.0f / (1.0f + expf(-z));
    }
}

extern "C" void kernel_launch(void* const* d_in, const int* in_sizes, int n_in,
                              void* d_out, int out_size)
{
    // Bind inputs by element count (robust to metadata ordering):
    //   x: 16384*10 = 163840 int32
    //   bias: 1 float32
    //   L: 10*100000 = 1,000,000 float32
    //   V: 10*10*100000*8 = 80,000,000 float32
    const int*   x    = nullptr;
    const float* bias = nullptr;
    const float* L    = nullptr;
    const float* V    = nullptr;
    for (int i = 0; i < n_in; ++i) {
        switch (in_sizes[i]) {
            case 163840:                 x    = (const int*)  d_in[i]; break;
            case 1:                      bias = (const float*)d_in[i]; break;
            case 1000000:                L    = (const float*)d_in[i]; break;
            case 80000000:               V    = (const float*)d_in[i]; break;
            default: break;
        }
    }
    float* out = (float*)d_out;

    const int grid = BATCH / ROWS_PER_BLOCK;   // 512
    ffm_kernel<<<grid, THREADS>>>(x, bias, L, V, out);
}

// round 2
// speedup vs baseline: 1.1509x; 1.1509x over previous
#include <cuda_runtime.h>
#include <math.h>

#define NUM_FIELDS 10
#define VOCAB      100000
#define EMBED      8
#define BATCH      16384

#define TPR            16                // threads cooperating on one row
#define ROWS_PER_BLOCK 16
#define THREADS        (TPR * ROWS_PER_BLOCK)   // 256
#define NPAIRS         45                // 10 choose 2
#define PAIRS_PER_T    3                 // ceil(45/16)

__global__ __launch_bounds__(THREADS)
void ffm_kernel(const int*   __restrict__ x,
                const float* __restrict__ bias,
                const float* __restrict__ L,
                const float* __restrict__ V,
                float*       __restrict__ out)
{
    __shared__ int sx[ROWS_PER_BLOCK][NUM_FIELDS];
    __shared__ int sI[NPAIRS], sJ[NPAIRS];
    __shared__ int sOij[NPAIRS], sOji[NPAIRS];

    const int tid = threadIdx.x;

    // ---- build pair table (once per block) ----
    if (tid < NPAIRS) {
        int p = tid;
        int i = 0, rem = p;
        while (rem >= (NUM_FIELDS - 1 - i)) { rem -= (NUM_FIELDS - 1 - i); ++i; }
        int j = i + 1 + rem;
        sI[p] = i;
        sJ[p] = j;
        sOij[p] = (i * NUM_FIELDS + j) * VOCAB;
        sOji[p] = (j * NUM_FIELDS + i) * VOCAB;
    }

    // ---- stage x tile for this block's rows ----
    const int row0 = blockIdx.x * ROWS_PER_BLOCK;
    for (int k = tid; k < ROWS_PER_BLOCK * NUM_FIELDS; k += THREADS) {
        ((int*)sx)[k] = x[row0 * NUM_FIELDS + k];
    }
    __syncthreads();

    const int r = tid / TPR;   // local row
    const int t = tid % TPR;   // slot within row group
    const int b = row0 + r;
    const int* xs = sx[r];

    float acc = 0.0f;

    // ---- second order: 45 pairs, strided by TPR, fully unrolled for MLP ----
    #pragma unroll
    for (int k = 0; k < PAIRS_PER_T; ++k) {
        const int p = t + k * TPR;
        if (p < NPAIRS) {
            const int i = sI[p];
            const int j = sJ[p];
            const float4* A  = reinterpret_cast<const float4*>(
                                   V + (size_t)(sOij[p] + xs[i]) * EMBED);
            const float4* Bv = reinterpret_cast<const float4*>(
                                   V + (size_t)(sOji[p] + xs[j]) * EMBED);
            const float4 a0 = __ldcs(A);
            const float4 a1 = __ldcs(A + 1);
            const float4 b0 = __ldcs(Bv);
            const float4 b1 = __ldcs(Bv + 1);
            acc += a0.x * b0.x + a0.y * b0.y + a0.z * b0.z + a0.w * b0.w
                 + a1.x * b1.x + a1.y * b1.y + a1.z * b1.z + a1.w * b1.w;
        }
    }

    // ---- first order: field t (only t < 10 participates) ----
    if (t < NUM_FIELDS) {
        acc += __ldcs(&L[t * VOCAB + xs[t]]);
    }

    // ---- reduce across the 16-lane row group ----
    acc += __shfl_down_sync(0xffffffffu, acc, 8, 16);
    acc += __shfl_down_sync(0xffffffffu, acc, 4, 16);
    acc += __shfl_down_sync(0xffffffffu, acc, 2, 16);
    acc += __shfl_down_sync(0xffffffffu, acc, 1, 16);

    if (t == 0 && b < BATCH) {
        const float z = acc + __ldg(bias);
        out[b] = 1.0f / (1.0f + expf(-z));
    }
}

extern "C" void kernel_launch(void* const* d_in, const int* in_sizes, int n_in,
                              void* d_out, int out_size)
{
    // Bind inputs by element count (robust to metadata ordering):
    //   x: 16384*10 = 163840 int32
    //   bias: 1 float32
    //   L: 10*100000 = 1,000,000 float32
    //   V: 10*10*100000*8 = 80,000,000 float32
    const int*   x    = nullptr;
    const float* bias = nullptr;
    const float* L    = nullptr;
    const float* V    = nullptr;
    for (int i = 0; i < n_in; ++i) {
        switch (in_sizes[i]) {
            case 163840:                 x    = (const int*)  d_in[i]; break;
            case 1:                      bias = (const float*)d_in[i]; break;
            case 1000000:                L    = (const float*)d_in[i]; break;
            case 80000000:               V    = (const float*)d_in[i]; break;
            default: break;
        }
    }
    float* out = (float*)d_out;

    const int grid = BATCH / ROWS_PER_BLOCK;   // 1024
    ffm_kernel<<<grid, THREADS>>>(x, bias, L, V, out);
}